// round 14
// baseline (speedup 1.0000x reference)
#include <cuda_runtime.h>
#include <math.h>
#include <stdint.h>

#define NROWS  115200
#define CDIM   256
#define THDIM  157
#define N2PAD  160
#define NPOSE_ 144
#define TILEM  64

// ---------------- device globals ----------------
__device__ float g_w23f [CDIM * N2PAD];
__device__ float g_cvec [CDIM];
__device__ float g_bvec2[N2PAD];
__device__ float g_tbias[N2PAD];

// int8 2-slice weights, swizzled: [chunk128][n][128B row]
__device__ __align__(16) char g_w1a_h8[2 * 256 * 128], g_w1a_l8[2 * 256 * 128];
__device__ __align__(16) char g_w1t_h8[2 * 256 * 128], g_w1t_l8[2 * 256 * 128];
__device__ __align__(16) char g_w23_h8[2 * 160 * 128], g_w23_l8[2 * 160 * 128];
__device__ float g_w1a_s[256], g_w1t_s[256], g_w23_s[N2PAD];

// ---------------- helpers ----------------
static __device__ __forceinline__ uint32_t smem_u32(const void* p) {
    uint32_t a;
    asm("{ .reg .u64 t; cvta.to.shared.u64 t, %1; cvt.u32.u64 %0, t; }" : "=r"(a) : "l"(p));
    return a;
}
static __device__ __forceinline__ void ldsm_x4(uint32_t* r, uint32_t a) {
    asm volatile("ldmatrix.sync.aligned.m8n8.x4.shared.b16 {%0,%1,%2,%3}, [%4];"
        : "=r"(r[0]), "=r"(r[1]), "=r"(r[2]), "=r"(r[3]) : "r"(a));
}
static __device__ __forceinline__ void ldsm_x2(uint32_t* r, uint32_t a) {
    asm volatile("ldmatrix.sync.aligned.m8n8.x2.shared.b16 {%0,%1}, [%2];"
        : "=r"(r[0]), "=r"(r[1]) : "r"(a));
}
static __device__ __forceinline__ void mma_s8(int* d, const uint32_t* a, const uint32_t* b) {
    asm volatile(
        "mma.sync.aligned.m16n8k32.row.col.s32.s8.s8.s32 "
        "{%0,%1,%2,%3}, {%4,%5,%6,%7}, {%8,%9}, {%0,%1,%2,%3};"
        : "+r"(d[0]), "+r"(d[1]), "+r"(d[2]), "+r"(d[3])
        : "r"(a[0]), "r"(a[1]), "r"(a[2]), "r"(a[3]), "r"(b[0]), "r"(b[1]));
}
#define CP_ASYNC16(sa, gp) \
    asm volatile("cp.async.cg.shared.global [%0], [%1], 16;" :: "r"(sa), "l"(gp))
#define CP_COMMIT() asm volatile("cp.async.commit_group;" ::: "memory")
#define CP_WAIT0()  asm volatile("cp.async.wait_group 0;" ::: "memory")
#define CP_WAIT1()  asm volatile("cp.async.wait_group 1;" ::: "memory")

__device__ __forceinline__ uint32_t swz(int row, int colbyte) {
    return (uint32_t)(row * 128 + (colbyte ^ ((row & 7) << 4)));
}
__device__ __forceinline__ void split2(int q, int& hi, int& lo) {
    hi = (q + 128) >> 8;  lo = q - (hi << 8);
}

// ---------------- prep kernels ----------------
__global__ void prep_w23(const float* __restrict__ W2, const float* __restrict__ W3)
{
    int k = blockIdx.x, n = threadIdx.x;
    float acc = 0.f;
    if (n < THDIM)
        for (int j = 0; j < CDIM; j++)
            acc = fmaf(W2[k * CDIM + j], W3[j * THDIM + n], acc);
    g_w23f[k * N2PAD + n] = (n < THDIM) ? acc : 0.f;
}

__global__ void prep_vecs(const float* __restrict__ W1, const float* __restrict__ b2,
                          const float* __restrict__ W3, const float* __restrict__ b3,
                          const float* __restrict__ cr, const float* __restrict__ sh,
                          const float* __restrict__ cam)
{
    __shared__ float th0[THDIM];
    int t = threadIdx.x;
    if (t < THDIM) {
        float v;
        if (t < NPOSE_)           v = cr[t];
        else if (t < NPOSE_ + 10) v = sh[t - NPOSE_];
        else                      v = cam[t - NPOSE_ - 10];
        th0[t] = v;
    }
    __syncthreads();
    {
        float acc = 0.f;
        for (int j = 0; j < THDIM; j++)
            acc = fmaf(th0[j], W1[(size_t)(CDIM + j) * CDIM + t], acc);
        g_cvec[t] = acc;
    }
    if (t < N2PAD) {
        float bv = 0.f;
        if (t < THDIM) {
            for (int j = 0; j < CDIM; j++)
                bv = fmaf(b2[j], W3[j * THDIM + t], bv);
            bv += b3[t];
        }
        g_bvec2[t] = bv;
        g_tbias[t] = bv + ((t < THDIM) ? th0[t] : 0.f);
    }
}

__global__ void conv_w1a(const float* __restrict__ W1)
{
    int n = threadIdx.x;
    float mx = 0.f;
    for (int k = 0; k < 256; k++) mx = fmaxf(mx, fabsf(W1[(size_t)k * CDIM + n]));
    float S = mx * 1.0204082f + 1e-30f;
    g_w1a_s[n] = S;
    float inv = 32768.f / S;
    for (int k = 0; k < 256; k++) {
        int q = __float2int_rn(W1[(size_t)k * CDIM + n] * inv), hi, lo;
        split2(q, hi, lo);
        size_t b = (size_t)(k >> 7) * 32768 + swz(n, k & 127);
        g_w1a_h8[b] = (char)hi;  g_w1a_l8[b] = (char)lo;
    }
}
__global__ void conv_w1t(const float* __restrict__ W1)
{
    int n = threadIdx.x;
    float mx = 0.f;
    for (int k = 0; k < THDIM; k++)
        mx = fmaxf(mx, fabsf(W1[(size_t)(CDIM + k) * CDIM + n]));
    float S = mx * 1.0204082f + 1e-30f;
    g_w1t_s[n] = S;
    float inv = 32768.f / S;
    for (int k = 0; k < 160; k++) {
        float v = (k < THDIM) ? W1[(size_t)(CDIM + k) * CDIM + n] : 0.f;
        int q = __float2int_rn(v * inv), hi, lo;
        split2(q, hi, lo);
        size_t b = (size_t)(k >> 7) * 32768 + swz(n, k & 127);
        g_w1t_h8[b] = (char)hi;  g_w1t_l8[b] = (char)lo;
    }
}
__global__ void conv_w23k(void)
{
    int n = threadIdx.x;
    float mx = 0.f;
    for (int k = 0; k < 256; k++) mx = fmaxf(mx, fabsf(g_w23f[k * N2PAD + n]));
    float S = mx * 1.0204082f + 1e-30f;
    g_w23_s[n] = S;
    float inv = 32768.f / S;
    for (int k = 0; k < 256; k++) {
        int q = __float2int_rn(g_w23f[k * N2PAD + n] * inv), hi, lo;
        split2(q, hi, lo);
        size_t b = (size_t)(k >> 7) * 20480 + swz(n, k & 127);
        g_w23_h8[b] = (char)hi;  g_w23_l8[b] = (char)lo;
    }
}

// ---------------- IMMA steps (k32 per step) ----------------
__device__ __forceinline__ void step3(uint32_t aHi, uint32_t aLo,
                                      uint32_t bHi, uint32_t bLo, int s,
                                      int (*aH)[4], int (*aM)[4],
                                      int lane, int wm, int wn)
{
    uint32_t Ah[4], Al[4];
    int row = wm * 16 + (lane & 15);
    int ca = s * 32 + ((lane >> 4) << 4);
    uint32_t ao = (uint32_t)(row * 128 + (ca ^ ((row & 7) << 4)));
    ldsm_x4(Ah, aHi + ao);
    ldsm_x4(Al, aLo + ao);
    int cb = s * 32 + (((lane >> 3) & 1) << 4);
#pragma unroll
    for (int nf = 0; nf < 8; nf++) {
        int rn = wn * 64 + nf * 8 + (lane & 7);
        uint32_t off = (uint32_t)(rn * 128 + (cb ^ ((lane & 7) << 4)));
        uint32_t Bh[2], Bl[2];
        ldsm_x2(Bh, bHi + off);
        ldsm_x2(Bl, bLo + off);
        mma_s8(aH[nf], Ah, Bh);
        mma_s8(aM[nf], Ah, Bl);
        mma_s8(aM[nf], Al, Bh);
    }
}
__device__ __forceinline__ void step4(uint32_t aHi, uint32_t aLo,
                                      uint32_t bHi, uint32_t bLo, int s,
                                      int (*aH)[4], int (*aM)[4], int (*aL)[4],
                                      int lane, int wm, int wn)
{
    uint32_t Ah[4], Al[4];
    int row = wm * 16 + (lane & 15);
    int ca = s * 32 + ((lane >> 4) << 4);
    uint32_t ao = (uint32_t)(row * 128 + (ca ^ ((row & 7) << 4)));
    ldsm_x4(Ah, aHi + ao);
    ldsm_x4(Al, aLo + ao);
    int cb = s * 32 + (((lane >> 3) & 1) << 4);
#pragma unroll
    for (int nf = 0; nf < 5; nf++) {
        int rn = wn * 40 + nf * 8 + (lane & 7);
        uint32_t off = (uint32_t)(rn * 128 + (cb ^ ((lane & 7) << 4)));
        uint32_t Bh[2], Bl[2];
        ldsm_x2(Bh, bHi + off);
        ldsm_x2(Bl, bLo + off);
        mma_s8(aH[nf], Ah, Bh);
        mma_s8(aM[nf], Ah, Bl);
        mma_s8(aM[nf], Al, Bh);
        mma_s8(aL[nf], Al, Bl);
    }
}

// ---------------- mega kernel ----------------
// SMEM (229440): [0,64K) fp32 staging (xw1 stride 256; final theta stride 160)
//  [64K,80K) U hi (2 chunks x 8K) | [80K,96K) U lo | [96K,224K) B | [224K,+64) scratch
__global__ void __launch_bounds__(512, 1)
mega(const float* __restrict__ x, const float* __restrict__ b1v,
     float* __restrict__ out)
{
    extern __shared__ char smem[];
    const uint32_t sb = smem_u32(smem);
    const int tid = threadIdx.x, lane = tid & 31, wid = tid >> 5;
    const int wm = wid & 3, wn = wid >> 2;
    const int bm = blockIdx.x * TILEM;
    const uint32_t UHI = sb + 65536, ULO = sb + 81920, BB = sb + 98304;
    float* scr = reinterpret_cast<float*>(smem + 229376);
    const int er = wm * 16 + (lane >> 2);
    const float C14 = 6.103515625e-05f, R8 = 0.00390625f, R16 = 1.52587890625e-05f;

    auto cpy32 = [&](const char* src, uint32_t dstoff) {
#pragma unroll
        for (int i = 0; i < 4; i++) {
            int j = tid + i * 512;
            CP_ASYNC16(BB + dstoff + j * 16, src + (size_t)j * 16);
        }
    };
    auto cpy20 = [&](const char* src, uint32_t dstoff) {
#pragma unroll
        for (int i = 0; i < 3; i++) {
            int j = tid + i * 512;
            if (j < 1280) CP_ASYNC16(BB + dstoff + j * 16, src + (size_t)j * 16);
        }
    };
    auto cpyT1 = [&]() {     // W1t chunk1: only k-bytes [0,32) per row
        int row = tid >> 1, seg = tid & 1;
        uint32_t o = (uint32_t)(row * 128 + ((seg * 16) ^ ((row & 7) << 4)));
        CP_ASYNC16(BB + 65536 + o, g_w1t_h8 + 32768 + o);
        CP_ASYNC16(BB + 98304 + o, g_w1t_l8 + 32768 + o);
    };
    auto issueW1a = [&]() {
        cpy32(g_w1a_h8, 0); cpy32(g_w1a_l8, 32768); CP_COMMIT();
        cpy32(g_w1a_h8 + 32768, 65536); cpy32(g_w1a_l8 + 32768, 98304); CP_COMMIT();
    };
    auto issueW1t = [&]() {
        cpy32(g_w1t_h8, 0); cpy32(g_w1t_l8, 32768); CP_COMMIT();
        cpyT1(); CP_COMMIT();
    };
    auto issueW23 = [&]() {
        cpy20(g_w23_h8, 0); cpy20(g_w23_l8, 20480); CP_COMMIT();
        cpy20(g_w23_h8 + 20480, 40960); cpy20(g_w23_l8 + 20480, 61440); CP_COMMIT();
    };
    auto rmax = [&](float v) -> float {
#pragma unroll
        for (int o = 16; o; o >>= 1) v = fmaxf(v, __shfl_xor_sync(0xffffffffu, v, o));
        if (lane == 0) scr[wid] = v;
        __syncthreads();
        float m = scr[0];
#pragma unroll
        for (int i = 1; i < 16; i++) m = fmaxf(m, scr[i]);
        __syncthreads();
        return m;
    };
    auto store_u8 = [&](int row, int col, float v0, float v1, float inv) {
        int q0 = __float2int_rn(v0 * inv), q1 = __float2int_rn(v1 * inv), h0, l0, h1, l1;
        split2(q0, h0, l0);  split2(q1, h1, l1);
        uint32_t off = (uint32_t)((col >> 7) * 8192) + swz(row, col & 127);
        *reinterpret_cast<unsigned short*>(smem + 65536 + off) =
            (unsigned short)((h0 & 255) | ((h1 & 255) << 8));
        *reinterpret_cast<unsigned short*>(smem + 81920 + off) =
            (unsigned short)((l0 & 255) | ((l1 & 255) << 8));
    };

    // N=256 GEMM: 2 B chunks prefetched as 2 groups; chunk1 has s1 steps.
    auto gemm256 = [&](int (*aH)[4], int (*aM)[4], int s1) {
        CP_WAIT1(); __syncthreads();
#pragma unroll
        for (int s = 0; s < 4; s++)
            step3(UHI, ULO, BB, BB + 32768, s, aH, aM, lane, wm, wn);
        CP_WAIT0(); __syncthreads();
        for (int s = 0; s < s1; s++)
            step3(UHI + 8192, ULO + 8192, BB + 65536, BB + 98304, s, aH, aM, lane, wm, wn);
        __syncthreads();
    };
    auto gemm160 = [&](int (*aH)[4], int (*aM)[4], int (*aL)[4]) {
        CP_WAIT1(); __syncthreads();
#pragma unroll
        for (int s = 0; s < 4; s++)
            step4(UHI, ULO, BB, BB + 20480, s, aH, aM, aL, lane, wm, wn);
        CP_WAIT0(); __syncthreads();
#pragma unroll
        for (int s = 0; s < 4; s++)
            step4(UHI + 8192, ULO + 8192, BB + 40960, BB + 61440, s, aH, aM, aL, lane, wm, wn);
        __syncthreads();
    };

    float th[5][4];
    float Su, St;

    issueW1a();

    // ---- load + quantize x into U ----
    {
        float4 xv[8];
        float l = 0.f;
#pragma unroll
        for (int i = 0; i < 8; i++) {
            int idx = tid + i * 512;
            int row = idx >> 6, g = idx & 63;
            xv[i] = *reinterpret_cast<const float4*>(x + (size_t)(bm + row) * CDIM + g * 4);
            l = fmaxf(l, fmaxf(fmaxf(fabsf(xv[i].x), fabsf(xv[i].y)),
                               fmaxf(fabsf(xv[i].z), fabsf(xv[i].w))));
        }
        float m = rmax(l);
        Su = m * 1.0204082f + 1e-30f;
        float inv = 32768.f / Su;
#pragma unroll
        for (int i = 0; i < 8; i++) {
            int idx = tid + i * 512;
            int row = idx >> 6, g = idx & 63;
            int q0 = __float2int_rn(xv[i].x * inv), q1 = __float2int_rn(xv[i].y * inv);
            int q2 = __float2int_rn(xv[i].z * inv), q3 = __float2int_rn(xv[i].w * inv);
            int h0, l0, h1, l1, h2, l2, h3, l3;
            split2(q0, h0, l0); split2(q1, h1, l1); split2(q2, h2, l2); split2(q3, h3, l3);
            uint32_t hp = (h0 & 255) | ((h1 & 255) << 8) | ((h2 & 255) << 16) | ((h3 & 255) << 24);
            uint32_t lp = (l0 & 255) | ((l1 & 255) << 8) | ((l2 & 255) << 16) | ((l3 & 255) << 24);
            uint32_t off = (uint32_t)((g >> 5) * 8192) + swz(row, (g * 4) & 127);
            *reinterpret_cast<uint32_t*>(smem + 65536 + off) = hp;
            *reinterpret_cast<uint32_t*>(smem + 81920 + off) = lp;
        }
    }

    // ---- K1 p1: xw1 = x @ W1a + b1 ; U = relu(xw1 + cvec) ----
    {
        int aH[8][4] = {}, aM[8][4] = {};
        gemm256(aH, aM, 4);
        issueW23();
        float uu[8][4];
        float l = 0.f;
#pragma unroll
        for (int nf = 0; nf < 8; nf++) {
            int col = wn * 64 + nf * 8 + (lane & 3) * 2;
            float g0 = Su * g_w1a_s[col] * C14, g1 = Su * g_w1a_s[col + 1] * C14;
            float v00 = fmaf(g0, (float)aH[nf][0] + (float)aM[nf][0] * R8, b1v[col]);
            float v01 = fmaf(g1, (float)aH[nf][1] + (float)aM[nf][1] * R8, b1v[col + 1]);
            float v10 = fmaf(g0, (float)aH[nf][2] + (float)aM[nf][2] * R8, b1v[col]);
            float v11 = fmaf(g1, (float)aH[nf][3] + (float)aM[nf][3] * R8, b1v[col + 1]);
            *reinterpret_cast<float2*>(smem + ((size_t)er * 256 + col) * 4) = make_float2(v00, v01);
            *reinterpret_cast<float2*>(smem + ((size_t)(er + 8) * 256 + col) * 4) = make_float2(v10, v11);
            uu[nf][0] = fmaxf(v00 + g_cvec[col], 0.f);
            uu[nf][1] = fmaxf(v01 + g_cvec[col + 1], 0.f);
            uu[nf][2] = fmaxf(v10 + g_cvec[col], 0.f);
            uu[nf][3] = fmaxf(v11 + g_cvec[col + 1], 0.f);
            l = fmaxf(l, fmaxf(fmaxf(uu[nf][0], uu[nf][1]), fmaxf(uu[nf][2], uu[nf][3])));
        }
        float m = rmax(l);
        Su = m * 1.0204082f + 1e-30f;
        float inv = 32768.f / Su;
#pragma unroll
        for (int nf = 0; nf < 8; nf++) {
            int col = wn * 64 + nf * 8 + (lane & 3) * 2;
            store_u8(er,     col, uu[nf][0], uu[nf][1], inv);
            store_u8(er + 8, col, uu[nf][2], uu[nf][3], inv);
        }
    }

    // ---- K1 p2: theta = U @ W23 + tbias ----
    {
        int aH[5][4] = {}, aM[5][4] = {}, aL[5][4] = {};
        gemm160(aH, aM, aL);
        issueW1t();
        float l = 0.f;
#pragma unroll
        for (int nf = 0; nf < 5; nf++) {
            int col = wn * 40 + nf * 8 + (lane & 3) * 2;
            float g0 = Su * g_w23_s[col] * C14, g1 = Su * g_w23_s[col + 1] * C14;
            th[nf][0] = fmaf(g0, (float)aH[nf][0] + (float)aM[nf][0] * R8 + (float)aL[nf][0] * R16, g_tbias[col]);
            th[nf][1] = fmaf(g1, (float)aH[nf][1] + (float)aM[nf][1] * R8 + (float)aL[nf][1] * R16, g_tbias[col + 1]);
            th[nf][2] = fmaf(g0, (float)aH[nf][2] + (float)aM[nf][2] * R8 + (float)aL[nf][2] * R16, g_tbias[col]);
            th[nf][3] = fmaf(g1, (float)aH[nf][3] + (float)aM[nf][3] * R8 + (float)aL[nf][3] * R16, g_tbias[col + 1]);
#pragma unroll
            for (int q = 0; q < 4; q++) l = fmaxf(l, fabsf(th[nf][q]));
        }
        float m = rmax(l);
        St = m * 1.0204082f + 1e-30f;
        float inv = 32768.f / St;
#pragma unroll
        for (int nf = 0; nf < 5; nf++) {
            int col = wn * 40 + nf * 8 + (lane & 3) * 2;
            store_u8(er,     col, th[nf][0], th[nf][1], inv);
            store_u8(er + 8, col, th[nf][2], th[nf][3], inv);
        }
    }

    // ---- iterations 2, 3 ----
#pragma unroll 1
    for (int it = 0; it < 2; it++) {
        // p1: h = relu(xw1 + theta @ W1t)
        {
            int aH[8][4] = {}, aM[8][4] = {};
            gemm256(aH, aM, 1);               // K=160: 4 + 1 k32 steps
            issueW23();
            float uu[8][4];
            float l = 0.f;
#pragma unroll
            for (int nf = 0; nf < 8; nf++) {
                int col = wn * 64 + nf * 8 + (lane & 3) * 2;
                float g0 = St * g_w1t_s[col] * C14, g1 = St * g_w1t_s[col + 1] * C14;
                float2 r0 = *reinterpret_cast<const float2*>(smem + ((size_t)er * 256 + col) * 4);
                float2 r1 = *reinterpret_cast<const float2*>(smem + ((size_t)(er + 8) * 256 + col) * 4);
                uu[nf][0] = fmaxf(fmaf(g0, (float)aH[nf][0] + (float)aM[nf][0] * R8, r0.x), 0.f);
                uu[nf][1] = fmaxf(fmaf(g1, (float)aH[nf][1] + (float)aM[nf][1] * R8, r0.y), 0.f);
                uu[nf][2] = fmaxf(fmaf(g0, (float)aH[nf][2] + (float)aM[nf][2] * R8, r1.x), 0.f);
                uu[nf][3] = fmaxf(fmaf(g1, (float)aH[nf][3] + (float)aM[nf][3] * R8, r1.y), 0.f);
                l = fmaxf(l, fmaxf(fmaxf(uu[nf][0], uu[nf][1]), fmaxf(uu[nf][2], uu[nf][3])));
            }
            float m = rmax(l);
            Su = m * 1.0204082f + 1e-30f;
            float inv = 32768.f / Su;
#pragma unroll
            for (int nf = 0; nf < 8; nf++) {
                int col = wn * 64 + nf * 8 + (lane & 3) * 2;
                store_u8(er,     col, uu[nf][0], uu[nf][1], inv);
                store_u8(er + 8, col, uu[nf][2], uu[nf][3], inv);
            }
        }
        // p2: theta += h @ W23 + bvec2
        {
            int aH[5][4] = {}, aM[5][4] = {}, aL[5][4] = {};
            gemm160(aH, aM, aL);
            if (it == 0) issueW1t();
            float l = 0.f;
#pragma unroll
            for (int nf = 0; nf < 5; nf++) {
                int col = wn * 40 + nf * 8 + (lane & 3) * 2;
                float g0 = Su * g_w23_s[col] * C14, g1 = Su * g_w23_s[col + 1] * C14;
                th[nf][0] += fmaf(g0, (float)aH[nf][0] + (float)aM[nf][0] * R8 + (float)aL[nf][0] * R16, g_bvec2[col]);
                th[nf][1] += fmaf(g1, (float)aH[nf][1] + (float)aM[nf][1] * R8 + (float)aL[nf][1] * R16, g_bvec2[col + 1]);
                th[nf][2] += fmaf(g0, (float)aH[nf][2] + (float)aM[nf][2] * R8 + (float)aL[nf][2] * R16, g_bvec2[col]);
                th[nf][3] += fmaf(g1, (float)aH[nf][3] + (float)aM[nf][3] * R8 + (float)aL[nf][3] * R16, g_bvec2[col + 1]);
#pragma unroll
                for (int q = 0; q < 4; q++) l = fmaxf(l, fabsf(th[nf][q]));
            }
            if (it == 0) {
                float m = rmax(l);
                St = m * 1.0204082f + 1e-30f;
                float inv = 32768.f / St;
#pragma unroll
                for (int nf = 0; nf < 5; nf++) {
                    int col = wn * 40 + nf * 8 + (lane & 3) * 2;
                    store_u8(er,     col, th[nf][0], th[nf][1], inv);
                    store_u8(er + 8, col, th[nf][2], th[nf][3], inv);
                }
            } else {
                __syncthreads();              // xw1 staging now dead
#pragma unroll
                for (int nf = 0; nf < 5; nf++) {
                    int col = wn * 40 + nf * 8 + (lane & 3) * 2;
                    if (col < N2PAD) {
                        *reinterpret_cast<float2*>(smem + ((size_t)er * 160 + col) * 4) =
                            make_float2(th[nf][0], th[nf][1]);
                        *reinterpret_cast<float2*>(smem + ((size_t)(er + 8) * 160 + col) * 4) =
                            make_float2(th[nf][2], th[nf][3]);
                    }
                }
            }
            __syncthreads();
        }
    }

    // ---- fused output: rot6d + betas/cam ----
    const float* ths = reinterpret_cast<const float*>(smem);
#pragma unroll
    for (int k2 = 0; k2 < 3; k2++) {
        int idx = tid + k2 * 512;
        int row = idx / 24, j = idx % 24;
        const float* p = ths + row * 160 + j * 6;
        float a1x = p[0], a2x = p[1], a1y = p[2], a2y = p[3], a1z = p[4], a2z = p[5];
        float n1 = fmaxf(sqrtf(a1x * a1x + a1y * a1y + a1z * a1z), 1e-12f);
        float b1x = a1x / n1, b1y = a1y / n1, b1z = a1z / n1;
        float d = b1x * a2x + b1y * a2y + b1z * a2z;
        float u2x = a2x - d * b1x, u2y = a2y - d * b1y, u2z = a2z - d * b1z;
        float n2 = fmaxf(sqrtf(u2x * u2x + u2y * u2y + u2z * u2z), 1e-12f);
        float b2x = u2x / n2, b2y = u2y / n2, b2z = u2z / n2;
        float b3x = b1y * b2z - b1z * b2y;
        float b3y = b1z * b2x - b1x * b2z;
        float b3z = b1x * b2y - b1y * b2x;
        float* o = out + ((size_t)(bm + row) * 24 + j) * 9;
        o[0] = b1x; o[1] = b2x; o[2] = b3x;
        o[3] = b1y; o[4] = b2y; o[5] = b3y;
        o[6] = b1z; o[7] = b2z; o[8] = b3z;
    }
    {
        const size_t OB  = (size_t)NROWS * 216;
        const size_t OB2 = OB + (size_t)NROWS * 10;
        for (int i = tid; i < TILEM * 13; i += 512) {
            int row = i / 13, k = i % 13;
            float v = ths[row * 160 + NPOSE_ + k];
            if (k < 10) out[OB + (size_t)(bm + row) * 10 + k] = v;
            else        out[OB2 + (size_t)(bm + row) * 3 + (k - 10)] = v;
        }
    }
}

// ---------------------------------------------------------------------------
extern "C" void kernel_launch(void* const* d_in, const int* in_sizes, int n_in,
                              void* d_out, int out_size)
{
    const float* x   = (const float*)d_in[0];
    const float* W1  = (const float*)d_in[2];
    const float* b1  = (const float*)d_in[3];
    const float* W2  = (const float*)d_in[4];
    const float* b2  = (const float*)d_in[5];
    const float* W3  = (const float*)d_in[6];
    const float* b3  = (const float*)d_in[7];
    const float* cr  = (const float*)d_in[8];
    const float* sh  = (const float*)d_in[9];
    const float* cam = (const float*)d_in[10];
    float* out = (float*)d_out;

    const size_t SMEM = 229440;
    cudaFuncSetAttribute(mega, cudaFuncAttributeMaxDynamicSharedMemorySize, SMEM);

    prep_w23<<<CDIM, N2PAD>>>(W2, W3);
    prep_vecs<<<1, CDIM>>>(W1, b2, W3, b3, cr, sh, cam);
    conv_w1a<<<1, 256>>>(W1);
    conv_w1t<<<1, 256>>>(W1);
    conv_w23k<<<1, N2PAD>>>();

    mega<<<NROWS / TILEM, 512, SMEM>>>(x, b1, out);
}

// round 16
// speedup vs baseline: 3.3196x; 3.3196x over previous
#include <cuda_runtime.h>
#include <cuda_fp16.h>
#include <math.h>
#include <stdint.h>

#define NROWS  115200
#define CDIM   256
#define THDIM  157
#define N2PAD  160
#define NPOSE_ 144
#define TILEM  64

// ---------------- device globals ----------------
__device__ float g_w23f [CDIM * N2PAD];
__device__ float g_cvec [CDIM];
__device__ float g_bvec2[N2PAD];
__device__ float g_tbias[N2PAD];

// fp16 hi/lo split weights, pre-swizzled: [chunk64][n][128B row, XOR-swizzled]
__device__ __align__(16) __half g_w1a_hi[4 * 256 * 64], g_w1a_lo[4 * 256 * 64]; // N=256,K=256
__device__ __align__(16) __half g_w1t_hi[3 * 256 * 64], g_w1t_lo[3 * 256 * 64]; // N=256,K=160(pad192)
__device__ __align__(16) __half g_w23_hi[4 * N2PAD * 64], g_w23_lo[4 * N2PAD * 64]; // N=160,K=256

// ---------------- helpers ----------------
static __device__ __forceinline__ uint32_t smem_u32(const void* p) {
    uint32_t a;
    asm("{ .reg .u64 t; cvta.to.shared.u64 t, %1; cvt.u32.u64 %0, t; }" : "=r"(a) : "l"(p));
    return a;
}
static __device__ __forceinline__ void ldsm_x4(uint32_t* r, uint32_t a) {
    asm volatile("ldmatrix.sync.aligned.m8n8.x4.shared.b16 {%0,%1,%2,%3}, [%4];"
        : "=r"(r[0]), "=r"(r[1]), "=r"(r[2]), "=r"(r[3]) : "r"(a));
}
static __device__ __forceinline__ void ldsm_x2(uint32_t* r, uint32_t a) {
    asm volatile("ldmatrix.sync.aligned.m8n8.x2.shared.b16 {%0,%1}, [%2];"
        : "=r"(r[0]), "=r"(r[1]) : "r"(a));
}
static __device__ __forceinline__ void mma_f16(float* d, const uint32_t* a, const uint32_t* b) {
    asm volatile(
        "mma.sync.aligned.m16n8k16.row.col.f32.f16.f16.f32 "
        "{%0,%1,%2,%3}, {%4,%5,%6,%7}, {%8,%9}, {%0,%1,%2,%3};"
        : "+f"(d[0]), "+f"(d[1]), "+f"(d[2]), "+f"(d[3])
        : "r"(a[0]), "r"(a[1]), "r"(a[2]), "r"(a[3]), "r"(b[0]), "r"(b[1]));
}
#define CP_ASYNC16(sa, gp) \
    asm volatile("cp.async.cg.shared.global [%0], [%1], 16;" :: "r"(sa), "l"(gp))
#define CP_COMMIT() asm volatile("cp.async.commit_group;" ::: "memory")
#define CP_WAIT0()  asm volatile("cp.async.wait_group 0;" ::: "memory")
#define CP_WAIT1()  asm volatile("cp.async.wait_group 1;" ::: "memory")

__device__ __forceinline__ uint32_t swz(int row, int colbyte) {
    return (uint32_t)(row * 128 + (colbyte ^ ((row & 7) << 4)));
}
static __device__ __forceinline__ unsigned short f16q(float v) {
    return __half_as_ushort(__float2half_rn(v));
}
static __device__ __forceinline__ float f16v(unsigned short u) {
    return __half2float(__ushort_as_half(u));
}
static __device__ __forceinline__ void put_w(__half* hiArr, __half* loArr,
                                             int Nrows, int k, int n, float v)
{
    unsigned short hb = f16q(v);
    unsigned short lb = f16q(v - f16v(hb));
    int chunk = k >> 6, kc = k & 63;
    size_t byte = (size_t)chunk * ((size_t)Nrows * 128) + swz(n, kc * 2);
    *(unsigned short*)((char*)hiArr + byte) = hb;
    *(unsigned short*)((char*)loArr + byte) = lb;
}

// ---------------- prep kernels (2 launches) ----------------
// prep_all: blocks [0,256) w23f rows | 256 vecs | [257,513) conv_w1a | [513,705) conv_w1t
__global__ void prep_all(const float* __restrict__ W1, const float* __restrict__ W2,
                         const float* __restrict__ b2, const float* __restrict__ W3,
                         const float* __restrict__ b3, const float* __restrict__ cr,
                         const float* __restrict__ sh, const float* __restrict__ cam)
{
    int bid = blockIdx.x, t = threadIdx.x;
    if (bid < 256) {
        if (t < N2PAD) {
            float acc = 0.f;
            if (t < THDIM)
                for (int j = 0; j < CDIM; j++)
                    acc = fmaf(W2[bid * CDIM + j], W3[j * THDIM + t], acc);
            g_w23f[bid * N2PAD + t] = (t < THDIM) ? acc : 0.f;
        }
    } else if (bid == 256) {
        __shared__ float th0[THDIM];
        if (t < THDIM) {
            float v;
            if (t < NPOSE_)           v = cr[t];
            else if (t < NPOSE_ + 10) v = sh[t - NPOSE_];
            else                      v = cam[t - NPOSE_ - 10];
            th0[t] = v;
        }
        __syncthreads();
        {
            float acc = 0.f;
            for (int j = 0; j < THDIM; j++)
                acc = fmaf(th0[j], W1[(size_t)(CDIM + j) * CDIM + t], acc);
            g_cvec[t] = acc;
        }
        if (t < N2PAD) {
            float bv = 0.f;
            if (t < THDIM) {
                for (int j = 0; j < CDIM; j++)
                    bv = fmaf(b2[j], W3[j * THDIM + t], bv);
                bv += b3[t];
            }
            g_bvec2[t] = bv;
            g_tbias[t] = bv + ((t < THDIM) ? th0[t] : 0.f);
        }
    } else if (bid < 513) {
        int idx = (bid - 257) * 256 + t;
        int k = idx >> 8, n = idx & 255;
        put_w(g_w1a_hi, g_w1a_lo, 256, k, n, W1[(size_t)k * CDIM + n]);
    } else {
        int idx = (bid - 513) * 256 + t;     // 192*256 elems
        int k = idx >> 8, n = idx & 255;
        float v = (k < THDIM) ? W1[(size_t)(CDIM + k) * CDIM + n] : 0.f;
        put_w(g_w1t_hi, g_w1t_lo, 256, k, n, v);
    }
}
__global__ void prep_w23c(void)    // conv_w23: depends on g_w23f
{
    int idx = blockIdx.x * 256 + threadIdx.x;
    if (idx >= 256 * N2PAD) return;
    int k = idx / N2PAD, n = idx % N2PAD;
    put_w(g_w23_hi, g_w23_lo, N2PAD, k, n, g_w23f[k * N2PAD + n]);
}

// ---------------- MMA passes (SC = k16-steps) ----------------
// pass1: acc += Ah*Bh + Al*Bh (== A*Bh).   pass2: acc += Ah*Bl.
template<int NF, int SC>
__device__ __forceinline__ void pass1s(uint32_t aHi, uint32_t aLo, uint32_t bHi,
                                       float (*acc)[4], int lane, int wm, int wn)
{
#pragma unroll
    for (int s = 0; s < SC; s++) {
        uint32_t Ah[4], Al[4], Bf[NF][2];
        int ca = s * 32 + ((lane >> 4) << 4);
        int cb = s * 32 + (((lane >> 3) & 1) << 4);
        int row = wm * 16 + (lane & 15);
        uint32_t aoff = (uint32_t)(row * 128 + (ca ^ ((row & 7) << 4)));
        ldsm_x4(Ah, aHi + aoff);
        ldsm_x4(Al, aLo + aoff);
#pragma unroll
        for (int nf = 0; nf < NF; nf++) {
            int rn = wn * (NF * 8) + nf * 8 + (lane & 7);
            uint32_t off = (uint32_t)(rn * 128 + (cb ^ ((lane & 7) << 4)));
            ldsm_x2(Bf[nf], bHi + off);
        }
#pragma unroll
        for (int nf = 0; nf < NF; nf++) mma_f16(acc[nf], Ah, Bf[nf]);
#pragma unroll
        for (int nf = 0; nf < NF; nf++) mma_f16(acc[nf], Al, Bf[nf]);
    }
}
template<int NF, int SC>
__device__ __forceinline__ void pass2s(uint32_t aHi, uint32_t bLo,
                                       float (*acc)[4], int lane, int wm, int wn)
{
#pragma unroll
    for (int s = 0; s < SC; s++) {
        uint32_t Ah[4], Bf[NF][2];
        int ca = s * 32 + ((lane >> 4) << 4);
        int cb = s * 32 + (((lane >> 3) & 1) << 4);
        int row = wm * 16 + (lane & 15);
        uint32_t aoff = (uint32_t)(row * 128 + (ca ^ ((row & 7) << 4)));
        ldsm_x4(Ah, aHi + aoff);
#pragma unroll
        for (int nf = 0; nf < NF; nf++) {
            int rn = wn * (NF * 8) + nf * 8 + (lane & 7);
            uint32_t off = (uint32_t)(rn * 128 + (cb ^ ((lane & 7) << 4)));
            ldsm_x2(Bf[nf], bLo + off);
        }
#pragma unroll
        for (int nf = 0; nf < NF; nf++) mma_f16(acc[nf], Ah, Bf[nf]);
    }
}
// 3-MMA single-pass for N=160 (B hi+lo resident)
template<int SC>
__device__ __forceinline__ void chunk160(uint32_t aHi, uint32_t aLo,
                                         uint32_t bH, uint32_t bL,
                                         float (*acc)[4], int lane, int wm, int wn)
{
#pragma unroll
    for (int s = 0; s < SC; s++) {
        uint32_t Ah[4], Al[4], Bh[5][2], Bl[5][2];
        int ca = s * 32 + ((lane >> 4) << 4);
        int cb = s * 32 + (((lane >> 3) & 1) << 4);
        int row = wm * 16 + (lane & 15);
        uint32_t aoff = (uint32_t)(row * 128 + (ca ^ ((row & 7) << 4)));
        ldsm_x4(Ah, aHi + aoff);
        ldsm_x4(Al, aLo + aoff);
#pragma unroll
        for (int nf = 0; nf < 5; nf++) {
            int rn = wn * 40 + nf * 8 + (lane & 7);
            uint32_t off = (uint32_t)(rn * 128 + (cb ^ ((lane & 7) << 4)));
            ldsm_x2(Bh[nf], bH + off);
            ldsm_x2(Bl[nf], bL + off);
        }
#pragma unroll
        for (int nf = 0; nf < 5; nf++) mma_f16(acc[nf], Ah, Bh[nf]);
#pragma unroll
        for (int nf = 0; nf < 5; nf++) mma_f16(acc[nf], Ah, Bl[nf]);
#pragma unroll
        for (int nf = 0; nf < 5; nf++) mma_f16(acc[nf], Al, Bh[nf]);
    }
}
// 2-MMA variant (final iteration): A*Bh only
template<int SC>
__device__ __forceinline__ void chunk160_2(uint32_t aHi, uint32_t aLo, uint32_t bH,
                                           float (*acc)[4], int lane, int wm, int wn)
{
#pragma unroll
    for (int s = 0; s < SC; s++) {
        uint32_t Ah[4], Al[4], Bh[5][2];
        int ca = s * 32 + ((lane >> 4) << 4);
        int cb = s * 32 + (((lane >> 3) & 1) << 4);
        int row = wm * 16 + (lane & 15);
        uint32_t aoff = (uint32_t)(row * 128 + (ca ^ ((row & 7) << 4)));
        ldsm_x4(Ah, aHi + aoff);
        ldsm_x4(Al, aLo + aoff);
#pragma unroll
        for (int nf = 0; nf < 5; nf++) {
            int rn = wn * 40 + nf * 8 + (lane & 7);
            uint32_t off = (uint32_t)(rn * 128 + (cb ^ ((lane & 7) << 4)));
            ldsm_x2(Bh[nf], bH + off);
        }
#pragma unroll
        for (int nf = 0; nf < 5; nf++) mma_f16(acc[nf], Ah, Bh[nf]);
#pragma unroll
        for (int nf = 0; nf < 5; nf++) mma_f16(acc[nf], Al, Bh[nf]);
    }
}

// ---------------- mega kernel ----------------
// SMEM (212992): [0,64K) fp32 staging (xw1 stride 256; final theta stride 160)
//   [64K,96K) U hi (4 chunks x 8K) | [96K,128K) U lo | [128K,208K) B region
__global__ void __launch_bounds__(512, 1)
mega(const float* __restrict__ x, const float* __restrict__ b1v,
     float* __restrict__ out)
{
    extern __shared__ char smem[];
    const uint32_t sb = smem_u32(smem);
    const int tid = threadIdx.x, lane = tid & 31, wid = tid >> 5;
    const int wm = wid & 3, wn = wid >> 2;
    const int bm = blockIdx.x * TILEM;
    const uint32_t UHI = sb + 65536, ULO = sb + 98304, BB = sb + 131072;
    const uint32_t S0 = BB, S1 = BB + 32768;
    const int er = wm * 16 + (lane >> 2);

    auto store_u = [&](int row, int col, float ux, float uy) {
        unsigned short h0 = f16q(ux), h1 = f16q(uy);
        unsigned short l0 = f16q(ux - f16v(h0)), l1 = f16q(uy - f16v(h1));
        uint32_t off = (uint32_t)((col >> 6) * 8192) + swz(row, (col & 63) * 2);
        *reinterpret_cast<uint32_t*>(smem + 65536 + off) = (uint32_t)h0 | ((uint32_t)h1 << 16);
        *reinterpret_cast<uint32_t*>(smem + 98304 + off) = (uint32_t)l0 | ((uint32_t)l1 << 16);
    };
    auto cpyB32 = [&](const __half* src, int c, uint32_t dst) {
        const char* s = (const char*)src + (size_t)c * 32768;
#pragma unroll
        for (int i = 0; i < 4; i++) {
            int j = tid + i * 512;
            CP_ASYNC16(dst + j * 16, s + (size_t)j * 16);
        }
    };
    auto cpyB20 = [&](int c, int buf) {           // W23 hi+lo pair
        const char* sh = (const char*)g_w23_hi + (size_t)c * 20480;
        const char* sl = (const char*)g_w23_lo + (size_t)c * 20480;
        uint32_t dh = BB + buf * 40960, dl = dh + 20480;
#pragma unroll
        for (int i = 0; i < 3; i++) {
            int j = tid + i * 512;
            if (j < 1280) {
                CP_ASYNC16(dh + j * 16, sh + (size_t)j * 16);
                CP_ASYNC16(dl + j * 16, sl + (size_t)j * 16);
            }
        }
    };
    auto cpyB20h = [&](int c, int buf) {          // W23 hi only (2-MMA path)
        const char* sh = (const char*)g_w23_hi + (size_t)c * 20480;
        uint32_t dh = BB + buf * 20480;
#pragma unroll
        for (int i = 0; i < 3; i++) {
            int j = tid + i * 512;
            if (j < 1280) CP_ASYNC16(dh + j * 16, sh + (size_t)j * 16);
        }
    };

    float th[5][4];

    // ======== K1 phase 1: xw1 = x @ W1a + b1 (A streamed from global) ========
    {
        float acc[8][4];
#pragma unroll
        for (int i = 0; i < 8; i++)
#pragma unroll
            for (int q = 0; q < 4; q++) acc[i][q] = 0.f;

        float4 aR[2];
        auto loadAg = [&](int c) {
#pragma unroll
            for (int i = 0; i < 2; i++) {
                int idx = tid + i * 512;
                int row = idx >> 4, f4 = idx & 15;
                aR[i] = *reinterpret_cast<const float4*>(
                    x + (size_t)(bm + row) * CDIM + (c << 6) + f4 * 4);
            }
        };
        auto storeA = [&](int buf) {
            char* hi = smem + 65536 + buf * 16384;
            char* lo = hi + 8192;
#pragma unroll
            for (int i = 0; i < 2; i++) {
                int idx = tid + i * 512;
                int row = idx >> 4, f4 = idx & 15;
                float4 v = aR[i];
                unsigned short h0 = f16q(v.x), h1 = f16q(v.y), h2 = f16q(v.z), h3 = f16q(v.w);
                unsigned short l0 = f16q(v.x - f16v(h0)), l1 = f16q(v.y - f16v(h1));
                unsigned short l2 = f16q(v.z - f16v(h2)), l3 = f16q(v.w - f16v(h3));
                uint2 hv = make_uint2((uint32_t)h0 | ((uint32_t)h1 << 16),
                                      (uint32_t)h2 | ((uint32_t)h3 << 16));
                uint2 lv = make_uint2((uint32_t)l0 | ((uint32_t)l1 << 16),
                                      (uint32_t)l2 | ((uint32_t)l3 << 16));
                uint32_t off = swz(row, f4 * 8);
                *reinterpret_cast<uint2*>(hi + off) = hv;
                *reinterpret_cast<uint2*>(lo + off) = lv;
            }
        };

        cpyB32(g_w1a_hi, 0, S0); CP_COMMIT();
        loadAg(0); storeA(0);
        CP_WAIT0(); __syncthreads();
#pragma unroll
        for (int c = 0; c < 4; c++) {
            cpyB32(g_w1a_lo, c, S1); CP_COMMIT();
            if (c < 3) loadAg(c + 1);
            uint32_t aHi = sb + 65536 + (c & 1) * 16384, aLo = aHi + 8192;
            pass1s<8, 4>(aHi, aLo, S0, acc, lane, wm, wn);
            __syncthreads();
            if (c < 3) { cpyB32(g_w1a_hi, c + 1, S0); CP_COMMIT(); CP_WAIT1(); }
            else       { CP_WAIT0(); }
            __syncthreads();
            pass2s<8, 4>(aHi, S1, acc, lane, wm, wn);
            if (c < 3) storeA((c + 1) & 1);
            CP_WAIT0();
            __syncthreads();
        }
#pragma unroll
        for (int nf = 0; nf < 8; nf++) {
            int col = wn * 64 + nf * 8 + (lane & 3) * 2;
            float bx = __ldg(b1v + col), by = __ldg(b1v + col + 1);
            float v00 = acc[nf][0] + bx, v01 = acc[nf][1] + by;
            float v10 = acc[nf][2] + bx, v11 = acc[nf][3] + by;
            *reinterpret_cast<float2*>(smem + ((size_t)er * 256 + col) * 4) = make_float2(v00, v01);
            *reinterpret_cast<float2*>(smem + ((size_t)(er + 8) * 256 + col) * 4) = make_float2(v10, v11);
            float cx = g_cvec[col], cy = g_cvec[col + 1];
            store_u(er,     col, fmaxf(v00 + cx, 0.f), fmaxf(v01 + cy, 0.f));
            store_u(er + 8, col, fmaxf(v10 + cx, 0.f), fmaxf(v11 + cy, 0.f));
        }
        __syncthreads();
    }

    // 3-MMA N=160 runner
    auto run_p2 = [&](float (*ac2)[4]) {
        cpyB20(0, 0); CP_COMMIT();
        CP_WAIT0(); __syncthreads();
#pragma unroll
        for (int c = 0; c < 4; c++) {
            if (c < 3) { cpyB20(c + 1, (c + 1) & 1); CP_COMMIT(); }
            uint32_t bH = BB + (c & 1) * 40960, bL = bH + 20480;
            chunk160<4>(UHI + c * 8192, ULO + c * 8192, bH, bL, ac2, lane, wm, wn);
            if (c < 3) CP_WAIT0();
            __syncthreads();
        }
    };
    // 2-MMA N=160 runner (final iteration)
    auto run_p2h = [&](float (*ac2)[4]) {
        cpyB20h(0, 0); CP_COMMIT();
        CP_WAIT0(); __syncthreads();
#pragma unroll
        for (int c = 0; c < 4; c++) {
            if (c < 3) { cpyB20h(c + 1, (c + 1) & 1); CP_COMMIT(); }
            uint32_t bH = BB + (c & 1) * 20480;
            chunk160_2<4>(UHI + c * 8192, ULO + c * 8192, bH, ac2, lane, wm, wn);
            if (c < 3) CP_WAIT0();
            __syncthreads();
        }
    };

    // ======== K1 phase 2: theta = U @ W23 + tbias ========
    {
        float ac2[5][4];
#pragma unroll
        for (int i = 0; i < 5; i++)
#pragma unroll
            for (int q = 0; q < 4; q++) ac2[i][q] = 0.f;
        run_p2(ac2);
#pragma unroll
        for (int nf = 0; nf < 5; nf++) {
            int col = wn * 40 + nf * 8 + (lane & 3) * 2;
            float bx = g_tbias[col], by = g_tbias[col + 1];
            th[nf][0] = ac2[nf][0] + bx;  th[nf][1] = ac2[nf][1] + by;
            th[nf][2] = ac2[nf][2] + bx;  th[nf][3] = ac2[nf][3] + by;
            store_u(er,     col, th[nf][0], th[nf][1]);
            store_u(er + 8, col, th[nf][2], th[nf][3]);
        }
        __syncthreads();
    }

    // ======== iterations 2 (3-MMA), 3 (2-MMA) ========
#pragma unroll 1
    for (int it = 0; it < 2; it++) {
        // phase 1: h = relu(xw1 + theta @ W1t); THS chunks {4,4,2} k16-steps
        {
            float acc[8][4];
#pragma unroll
            for (int i = 0; i < 8; i++)
#pragma unroll
                for (int q = 0; q < 4; q++) acc[i][q] = 0.f;

            if (it == 0) {
                cpyB32(g_w1t_hi, 0, S0); CP_COMMIT();
                CP_WAIT0(); __syncthreads();
#pragma unroll
                for (int c = 0; c < 3; c++) {
                    cpyB32(g_w1t_lo, c, S1); CP_COMMIT();
                    uint32_t aHi = UHI + c * 8192, aLo = ULO + c * 8192;
                    if (c < 2) pass1s<8, 4>(aHi, aLo, S0, acc, lane, wm, wn);
                    else       pass1s<8, 2>(aHi, aLo, S0, acc, lane, wm, wn);
                    __syncthreads();
                    if (c < 2) { cpyB32(g_w1t_hi, c + 1, S0); CP_COMMIT(); CP_WAIT1(); }
                    else       { CP_WAIT0(); }
                    __syncthreads();
                    if (c < 2) pass2s<8, 4>(aHi, S1, acc, lane, wm, wn);
                    else       pass2s<8, 2>(aHi, S1, acc, lane, wm, wn);
                    CP_WAIT0();
                    __syncthreads();
                }
            } else {
                // 2-MMA: A*Bh only, hi chunks double-buffered S0/S1
                cpyB32(g_w1t_hi, 0, S0); CP_COMMIT();
                CP_WAIT0(); __syncthreads();
#pragma unroll
                for (int c = 0; c < 3; c++) {
                    if (c < 2) { cpyB32(g_w1t_hi, c + 1, (c & 1) ? S0 : S1); CP_COMMIT(); }
                    uint32_t bS = (c & 1) ? S1 : S0;
                    uint32_t aHi = UHI + c * 8192, aLo = ULO + c * 8192;
                    if (c < 2) pass1s<8, 4>(aHi, aLo, bS, acc, lane, wm, wn);
                    else       pass1s<8, 2>(aHi, aLo, bS, acc, lane, wm, wn);
                    if (c < 2) CP_WAIT0();
                    __syncthreads();
                }
            }
#pragma unroll
            for (int nf = 0; nf < 8; nf++) {
                int col = wn * 64 + nf * 8 + (lane & 3) * 2;
                float2 r0 = *reinterpret_cast<const float2*>(smem + ((size_t)er * 256 + col) * 4);
                float2 r1 = *reinterpret_cast<const float2*>(smem + ((size_t)(er + 8) * 256 + col) * 4);
                store_u(er,     col, fmaxf(acc[nf][0] + r0.x, 0.f), fmaxf(acc[nf][1] + r0.y, 0.f));
                store_u(er + 8, col, fmaxf(acc[nf][2] + r1.x, 0.f), fmaxf(acc[nf][3] + r1.y, 0.f));
            }
            __syncthreads();
        }
        // phase 2: theta += h @ W23 + bvec2
        {
            float ac2[5][4];
#pragma unroll
            for (int i = 0; i < 5; i++)
#pragma unroll
                for (int q = 0; q < 4; q++) ac2[i][q] = 0.f;
            if (it == 0) run_p2(ac2);
            else         run_p2h(ac2);
#pragma unroll
            for (int nf = 0; nf < 5; nf++) {
                int col = wn * 40 + nf * 8 + (lane & 3) * 2;
                float bx = g_bvec2[col], by = g_bvec2[col + 1];
                th[nf][0] += ac2[nf][0] + bx;  th[nf][1] += ac2[nf][1] + by;
                th[nf][2] += ac2[nf][2] + bx;  th[nf][3] += ac2[nf][3] + by;
            }
            if (it == 0) {
#pragma unroll
                for (int nf = 0; nf < 5; nf++) {
                    int col = wn * 40 + nf * 8 + (lane & 3) * 2;
                    store_u(er,     col, th[nf][0], th[nf][1]);
                    store_u(er + 8, col, th[nf][2], th[nf][3]);
                }
            } else {
                __syncthreads();             // xw1 staging now dead
#pragma unroll
                for (int nf = 0; nf < 5; nf++) {
                    int col = wn * 40 + nf * 8 + (lane & 3) * 2;
                    *reinterpret_cast<float2*>(smem + ((size_t)er * 160 + col) * 4) =
                        make_float2(th[nf][0], th[nf][1]);
                    *reinterpret_cast<float2*>(smem + ((size_t)(er + 8) * 160 + col) * 4) =
                        make_float2(th[nf][2], th[nf][3]);
                }
            }
            __syncthreads();
        }
    }

    // ======== fused output: rot6d + betas/cam ========
    const float* ths = reinterpret_cast<const float*>(smem);
#pragma unroll
    for (int k2 = 0; k2 < 3; k2++) {
        int idx = tid + k2 * 512;
        int row = idx / 24, j = idx % 24;
        const float* p = ths + row * 160 + j * 6;
        float a1x = p[0], a2x = p[1], a1y = p[2], a2y = p[3], a1z = p[4], a2z = p[5];
        float n1 = fmaxf(sqrtf(a1x * a1x + a1y * a1y + a1z * a1z), 1e-12f);
        float b1x = a1x / n1, b1y = a1y / n1, b1z = a1z / n1;
        float d = b1x * a2x + b1y * a2y + b1z * a2z;
        float u2x = a2x - d * b1x, u2y = a2y - d * b1y, u2z = a2z - d * b1z;
        float n2 = fmaxf(sqrtf(u2x * u2x + u2y * u2y + u2z * u2z), 1e-12f);
        float b2x = u2x / n2, b2y = u2y / n2, b2z = u2z / n2;
        float b3x = b1y * b2z - b1z * b2y;
        float b3y = b1z * b2x - b1x * b2z;
        float b3z = b1x * b2y - b1y * b2x;
        float* o = out + ((size_t)(bm + row) * 24 + j) * 9;
        o[0] = b1x; o[1] = b2x; o[2] = b3x;
        o[3] = b1y; o[4] = b2y; o[5] = b3y;
        o[6] = b1z; o[7] = b2z; o[8] = b3z;
    }
    {
        const size_t OB  = (size_t)NROWS * 216;
        const size_t OB2 = OB + (size_t)NROWS * 10;
        for (int i = tid; i < TILEM * 13; i += 512) {
            int row = i / 13, k = i % 13;
            float v = ths[row * 160 + NPOSE_ + k];
            if (k < 10) out[OB + (size_t)(bm + row) * 10 + k] = v;
            else        out[OB2 + (size_t)(bm + row) * 3 + (k - 10)] = v;
        }
    }
}

// ---------------------------------------------------------------------------
extern "C" void kernel_launch(void* const* d_in, const int* in_sizes, int n_in,
                              void* d_out, int out_size)
{
    const float* x   = (const float*)d_in[0];
    // d_in[1] = pred_class (unused)
    const float* W1  = (const float*)d_in[2];
    const float* b1  = (const float*)d_in[3];
    const float* W2  = (const float*)d_in[4];
    const float* b2  = (const float*)d_in[5];
    const float* W3  = (const float*)d_in[6];
    const float* b3  = (const float*)d_in[7];
    const float* cr  = (const float*)d_in[8];
    const float* sh  = (const float*)d_in[9];
    const float* cam = (const float*)d_in[10];
    float* out = (float*)d_out;

    const size_t SMEM = 212992;     // 208KB
    cudaFuncSetAttribute(mega, cudaFuncAttributeMaxDynamicSharedMemorySize, SMEM);

    prep_all<<<705, 256>>>(W1, W2, b2, W3, b3, cr, sh, cam);
    prep_w23c<<<160, 256>>>();
    mega<<<NROWS / TILEM, 512, SMEM>>>(x, b1, out);
}